// round 1
// baseline (speedup 1.0000x reference)
#include <cuda_runtime.h>
#include <math.h>

// ---------------------------------------------------------------------------
// Problem constants
// ---------------------------------------------------------------------------
#define BATCH 2
#define SEQ   2048
#define EMBD  1024
#define NHEAD 16
#define HDIM  64
#define MROWS (BATCH * SEQ)          // 4096
#define FFN   (4 * EMBD)             // 4096
#define JOINED 25

// ---------------------------------------------------------------------------
// Scratch buffers (device globals: no allocation allowed)
// ---------------------------------------------------------------------------
__device__ __align__(128) float g_xln [MROWS * EMBD];   // LN1 output
__device__ __align__(128) float g_q   [MROWS * EMBD];
__device__ __align__(128) float g_k   [MROWS * EMBD];
__device__ __align__(128) float g_v   [MROWS * EMBD];
__device__ __align__(128) float g_attn[MROWS * EMBD];   // attention output (pre-proj)
__device__ __align__(128) float g_h1  [MROWS * EMBD];   // residual2 = attn@Wp + bp + hidden
__device__ __align__(128) float g_x2  [MROWS * EMBD];   // LN2 output
__device__ __align__(128) float g_mh  [MROWS * FFN];    // GELU(x2@W1+b1)

// ---------------------------------------------------------------------------
// LayerNorm: one block (256 threads) per row of 1024
// ---------------------------------------------------------------------------
__global__ void ln_kernel(const float* __restrict__ x,
                          const float* __restrict__ g,
                          const float* __restrict__ beta,
                          float* __restrict__ y) {
    int row = blockIdx.x;
    int tid = threadIdx.x;                      // 256
    const float4* xr = (const float4*)(x + (size_t)row * EMBD);
    float4 v = xr[tid];
    float s  = v.x + v.y + v.z + v.w;
    float ss = v.x*v.x + v.y*v.y + v.z*v.z + v.w*v.w;
    #pragma unroll
    for (int o = 16; o > 0; o >>= 1) {
        s  += __shfl_xor_sync(0xffffffffu, s,  o);
        ss += __shfl_xor_sync(0xffffffffu, ss, o);
    }
    __shared__ float sh[16];
    __shared__ float mean_s, rstd_s;
    int wid = tid >> 5, lane = tid & 31;
    if (lane == 0) { sh[wid] = s; sh[wid + 8] = ss; }
    __syncthreads();
    if (tid == 0) {
        float ts = 0.f, tss = 0.f;
        #pragma unroll
        for (int i = 0; i < 8; i++) { ts += sh[i]; tss += sh[i + 8]; }
        float mean = ts * (1.0f / EMBD);
        float var  = tss * (1.0f / EMBD) - mean * mean;
        mean_s = mean;
        rstd_s = rsqrtf(var + 1e-5f);
    }
    __syncthreads();
    float mean = mean_s, rstd = rstd_s;
    float4 gv = ((const float4*)g)[tid];
    float4 bv = ((const float4*)beta)[tid];
    float4 o;
    o.x = (v.x - mean) * rstd * gv.x + bv.x;
    o.y = (v.y - mean) * rstd * gv.y + bv.y;
    o.z = (v.z - mean) * rstd * gv.z + bv.z;
    o.w = (v.w - mean) * rstd * gv.w + bv.w;
    ((float4*)(y + (size_t)row * EMBD))[tid] = o;
}

// ---------------------------------------------------------------------------
// Tiled SGEMM: C[M,N] = A[M,K] @ B[K,N] + bias[N]  (+ epilogue)
// 128x128 tile, BK=8, 256 threads, 8x8 per thread. M,N,K multiples of 128/8.
// ---------------------------------------------------------------------------
#define EPI_NONE 0
#define EPI_GELU 1
#define EPI_ADD  2

__device__ __forceinline__ float gelu_exact(float x) {
    return 0.5f * x * (1.0f + erff(x * 0.70710678118654752f));
}

template <int EPI>
__global__ void __launch_bounds__(256)
sgemm_kernel(const float* __restrict__ A, const float* __restrict__ B,
             const float* __restrict__ bias, const float* __restrict__ add,
             float* __restrict__ C, int M, int N, int K) {
    __shared__ float As[8][128];
    __shared__ float Bs[8][128];
    const int tid = threadIdx.x;
    const int tx = tid & 15;          // 0..15 -> col group
    const int ty = tid >> 4;          // 0..15 -> row group
    const int row0 = blockIdx.y * 128;
    const int col0 = blockIdx.x * 128;

    const int ar = tid >> 1;          // 0..127
    const int ac = (tid & 1) * 4;     // 0 or 4
    const int br = tid >> 5;          // 0..7
    const int bc = (tid & 31) * 4;    // 0..124

    float acc[8][8];
    #pragma unroll
    for (int i = 0; i < 8; i++)
        #pragma unroll
        for (int j = 0; j < 8; j++) acc[i][j] = 0.f;

    for (int k0 = 0; k0 < K; k0 += 8) {
        float4 av = *(const float4*)&A[(size_t)(row0 + ar) * K + k0 + ac];
        As[ac + 0][ar] = av.x;
        As[ac + 1][ar] = av.y;
        As[ac + 2][ar] = av.z;
        As[ac + 3][ar] = av.w;
        *(float4*)&Bs[br][bc] = *(const float4*)&B[(size_t)(k0 + br) * N + col0 + bc];
        __syncthreads();
        #pragma unroll
        for (int kk = 0; kk < 8; kk++) {
            float a[8], b[8];
            *(float4*)&a[0] = *(float4*)&As[kk][ty * 8];
            *(float4*)&a[4] = *(float4*)&As[kk][ty * 8 + 4];
            *(float4*)&b[0] = *(float4*)&Bs[kk][tx * 8];
            *(float4*)&b[4] = *(float4*)&Bs[kk][tx * 8 + 4];
            #pragma unroll
            for (int i = 0; i < 8; i++)
                #pragma unroll
                for (int j = 0; j < 8; j++)
                    acc[i][j] += a[i] * b[j];
        }
        __syncthreads();
    }

    #pragma unroll
    for (int i = 0; i < 8; i++) {
        int r = row0 + ty * 8 + i;
        #pragma unroll
        for (int j4 = 0; j4 < 8; j4 += 4) {
            int c = col0 + tx * 8 + j4;
            float4 bsv = *(const float4*)&bias[c];
            float4 o;
            o.x = acc[i][j4 + 0] + bsv.x;
            o.y = acc[i][j4 + 1] + bsv.y;
            o.z = acc[i][j4 + 2] + bsv.z;
            o.w = acc[i][j4 + 3] + bsv.w;
            if (EPI == EPI_GELU) {
                o.x = gelu_exact(o.x); o.y = gelu_exact(o.y);
                o.z = gelu_exact(o.z); o.w = gelu_exact(o.w);
            } else if (EPI == EPI_ADD) {
                float4 adv = *(const float4*)&add[(size_t)r * N + c];
                o.x += adv.x; o.y += adv.y; o.z += adv.z; o.w += adv.w;
            }
            *(float4*)&C[(size_t)r * N + c] = o;
        }
    }
}

// ---------------------------------------------------------------------------
// Attention: flash-style, one query row per thread, 128 q-rows per block.
// Q/K/V layout: [B*S, EMBD] with head h occupying cols [h*64, h*64+64).
// mask: attend iff (k <= q) && (k % 25 != 24)
// ---------------------------------------------------------------------------
__global__ void __launch_bounds__(128)
attn_kernel(const float* __restrict__ Q, const float* __restrict__ K,
            const float* __restrict__ V, float* __restrict__ O) {
    const int tid = threadIdx.x;               // 128
    const int q   = blockIdx.x * 128 + tid;
    const int h   = blockIdx.y;
    const int b   = blockIdx.z;
    const size_t base = (size_t)b * SEQ * EMBD + (size_t)h * HDIM;

    float qr[64];
    {
        const float4* qp = (const float4*)(Q + base + (size_t)q * EMBD);
        #pragma unroll
        for (int d4 = 0; d4 < 16; d4++) {
            float4 v = qp[d4];
            qr[d4 * 4 + 0] = v.x * 0.125f;
            qr[d4 * 4 + 1] = v.y * 0.125f;
            qr[d4 * 4 + 2] = v.z * 0.125f;
            qr[d4 * 4 + 3] = v.w * 0.125f;
        }
    }

    float m = -1e30f, l = 0.f;
    float acc[64];
    #pragma unroll
    for (int d = 0; d < 64; d++) acc[d] = 0.f;

    __shared__ float Ks[16][64];
    __shared__ float Vs[16][64];

    const int ntiles = (blockIdx.x + 1) * 8;   // causal: keys up to block's last q
    const int lj = tid >> 3;                   // 0..15  key within tile
    const int lc = (tid & 7) * 8;              // 0..56  col offset

    for (int t = 0; t < ntiles; t++) {
        size_t krow = base + (size_t)(t * 16 + lj) * EMBD;
        *(float4*)&Ks[lj][lc]     = *(const float4*)(K + krow + lc);
        *(float4*)&Ks[lj][lc + 4] = *(const float4*)(K + krow + lc + 4);
        *(float4*)&Vs[lj][lc]     = *(const float4*)(V + krow + lc);
        *(float4*)&Vs[lj][lc + 4] = *(const float4*)(V + krow + lc + 4);
        __syncthreads();

        float sj[16];
        float tmax = -1e30f;
        #pragma unroll
        for (int jj = 0; jj < 16; jj++) {
            float s = 0.f;
            #pragma unroll
            for (int d4 = 0; d4 < 16; d4++) {
                float4 kv = *(const float4*)&Ks[jj][d4 * 4];
                s += qr[d4*4+0] * kv.x + qr[d4*4+1] * kv.y
                   + qr[d4*4+2] * kv.z + qr[d4*4+3] * kv.w;
            }
            int kidx = t * 16 + jj;
            bool ok = (kidx <= q) && (kidx % JOINED != (JOINED - 1));
            s = ok ? s : -1e30f;
            sj[jj] = s;
            tmax = fmaxf(tmax, s);
        }
        float mnew = fmaxf(m, tmax);
        float corr = __expf(m - mnew);
        l *= corr;
        #pragma unroll
        for (int d = 0; d < 64; d++) acc[d] *= corr;
        #pragma unroll
        for (int jj = 0; jj < 16; jj++) {
            float p = __expf(sj[jj] - mnew);
            l += p;
            #pragma unroll
            for (int d = 0; d < 64; d++) acc[d] += p * Vs[jj][d];
        }
        m = mnew;
        __syncthreads();
    }

    float inv = 1.0f / l;
    float4* op = (float4*)(O + base + (size_t)q * EMBD);
    #pragma unroll
    for (int d4 = 0; d4 < 16; d4++) {
        float4 o;
        o.x = acc[d4 * 4 + 0] * inv;
        o.y = acc[d4 * 4 + 1] * inv;
        o.z = acc[d4 * 4 + 2] * inv;
        o.w = acc[d4 * 4 + 3] * inv;
        op[d4] = o;
    }
}

// ---------------------------------------------------------------------------
// Host launcher
// ---------------------------------------------------------------------------
extern "C" void kernel_launch(void* const* d_in, const int* in_sizes, int n_in,
                              void* d_out, int out_size) {
    const float* hidden = (const float*)d_in[0];
    const float* Wq = (const float*)d_in[1];
    const float* bq = (const float*)d_in[2];
    const float* Wk = (const float*)d_in[3];
    const float* bk = (const float*)d_in[4];
    const float* Wv = (const float*)d_in[5];
    const float* bv = (const float*)d_in[6];
    const float* Wp = (const float*)d_in[7];
    const float* bp = (const float*)d_in[8];
    const float* ln1_g = (const float*)d_in[9];
    const float* ln1_b = (const float*)d_in[10];
    const float* ln2_g = (const float*)d_in[11];
    const float* ln2_b = (const float*)d_in[12];
    const float* W1 = (const float*)d_in[13];
    const float* b1 = (const float*)d_in[14];
    const float* W2 = (const float*)d_in[15];
    const float* b2 = (const float*)d_in[16];
    float* out = (float*)d_out;

    float *xln, *qb, *kb, *vb, *ab, *h1, *x2, *mh;
    cudaGetSymbolAddress((void**)&xln, g_xln);
    cudaGetSymbolAddress((void**)&qb,  g_q);
    cudaGetSymbolAddress((void**)&kb,  g_k);
    cudaGetSymbolAddress((void**)&vb,  g_v);
    cudaGetSymbolAddress((void**)&ab,  g_attn);
    cudaGetSymbolAddress((void**)&h1,  g_h1);
    cudaGetSymbolAddress((void**)&x2,  g_x2);
    cudaGetSymbolAddress((void**)&mh,  g_mh);

    // 1. LN1
    ln_kernel<<<MROWS, 256>>>(hidden, ln1_g, ln1_b, xln);

    // 2. QKV projections
    dim3 gemm_blk(256);
    dim3 grid_d(EMBD / 128, MROWS / 128);
    sgemm_kernel<EPI_NONE><<<grid_d, gemm_blk>>>(xln, Wq, bq, nullptr, qb, MROWS, EMBD, EMBD);
    sgemm_kernel<EPI_NONE><<<grid_d, gemm_blk>>>(xln, Wk, bk, nullptr, kb, MROWS, EMBD, EMBD);
    sgemm_kernel<EPI_NONE><<<grid_d, gemm_blk>>>(xln, Wv, bv, nullptr, vb, MROWS, EMBD, EMBD);

    // 3. Attention
    dim3 agrid(SEQ / 128, NHEAD, BATCH);
    attn_kernel<<<agrid, 128>>>(qb, kb, vb, ab);

    // 4. Output projection + residual
    sgemm_kernel<EPI_ADD><<<grid_d, gemm_blk>>>(ab, Wp, bp, hidden, h1, MROWS, EMBD, EMBD);

    // 5. LN2
    ln_kernel<<<MROWS, 256>>>(h1, ln2_g, ln2_b, x2);

    // 6. MLP up + GELU
    dim3 grid_f(FFN / 128, MROWS / 128);
    sgemm_kernel<EPI_GELU><<<grid_f, gemm_blk>>>(x2, W1, b1, nullptr, mh, MROWS, FFN, EMBD);

    // 7. MLP down + residual2 -> out
    sgemm_kernel<EPI_ADD><<<grid_d, gemm_blk>>>(mh, W2, b2, h1, out, MROWS, EMBD, FFN);
}

// round 4
// speedup vs baseline: 1.6848x; 1.6848x over previous
#include <cuda_runtime.h>
#include <cuda_bf16.h>
#include <math.h>
#include <stdint.h>

// ---------------------------------------------------------------------------
// Problem constants
// ---------------------------------------------------------------------------
#define BATCH 2
#define SEQ   2048
#define EMBD  1024
#define NHEAD 16
#define HDIM  64
#define MROWS (BATCH * SEQ)          // 4096
#define FFN   (4 * EMBD)             // 4096
#define JOINED 25

typedef __nv_bfloat16 bf16;
typedef __nv_bfloat162 bf162;

// ---------------------------------------------------------------------------
// Scratch (device globals — no allocation allowed)
// ---------------------------------------------------------------------------
// fp32 activations
__device__ __align__(128) float g_q  [MROWS * EMBD];
__device__ __align__(128) float g_k  [MROWS * EMBD];
__device__ __align__(128) float g_v  [MROWS * EMBD];
__device__ __align__(128) float g_h1 [MROWS * EMBD];
// bf16 hi/lo activation pairs
__device__ __align__(128) bf16 g_xlnh[MROWS * EMBD];
__device__ __align__(128) bf16 g_xlnl[MROWS * EMBD];
__device__ __align__(128) bf16 g_abh [MROWS * EMBD];
__device__ __align__(128) bf16 g_abl [MROWS * EMBD];
__device__ __align__(128) bf16 g_x2h [MROWS * EMBD];
__device__ __align__(128) bf16 g_x2l [MROWS * EMBD];
__device__ __align__(128) bf16 g_mhh [MROWS * FFN];
__device__ __align__(128) bf16 g_mhl [MROWS * FFN];
// bf16 hi/lo transposed weights [N, K]
__device__ __align__(128) bf16 g_wqh[EMBD * EMBD];
__device__ __align__(128) bf16 g_wql[EMBD * EMBD];
__device__ __align__(128) bf16 g_wkh[EMBD * EMBD];
__device__ __align__(128) bf16 g_wkl[EMBD * EMBD];
__device__ __align__(128) bf16 g_wvh[EMBD * EMBD];
__device__ __align__(128) bf16 g_wvl[EMBD * EMBD];
__device__ __align__(128) bf16 g_wph[EMBD * EMBD];
__device__ __align__(128) bf16 g_wpl[EMBD * EMBD];
__device__ __align__(128) bf16 g_w1h[FFN * EMBD];
__device__ __align__(128) bf16 g_w1l[FFN * EMBD];
__device__ __align__(128) bf16 g_w2h[EMBD * FFN];
__device__ __align__(128) bf16 g_w2l[EMBD * FFN];

// ---------------------------------------------------------------------------
// Small helpers
// ---------------------------------------------------------------------------
__device__ __forceinline__ uint32_t smem_to_u32(const void* p) {
    uint32_t a;
    asm("{ .reg .u64 t; cvta.to.shared.u64 t, %1; cvt.u32.u64 %0, t; }"
        : "=r"(a) : "l"(p));
    return a;
}

__device__ __forceinline__ void cp_async16(uint32_t dst, const void* src) {
    asm volatile("cp.async.cg.shared.global [%0], [%1], 16;" :: "r"(dst), "l"(src));
}
__device__ __forceinline__ void cp_commit() {
    asm volatile("cp.async.commit_group;");
}
template <int N>
__device__ __forceinline__ void cp_wait() {
    asm volatile("cp.async.wait_group %0;" :: "n"(N));
}

__device__ __forceinline__ void ldmx4(uint32_t (&r)[4], uint32_t addr) {
    asm volatile("ldmatrix.sync.aligned.m8n8.x4.shared.b16 {%0,%1,%2,%3}, [%4];"
        : "=r"(r[0]), "=r"(r[1]), "=r"(r[2]), "=r"(r[3]) : "r"(addr));
}

__device__ __forceinline__ void mma_bf16(float (&d)[4], const uint32_t (&a)[4],
                                         uint32_t b0, uint32_t b1) {
    asm volatile(
        "mma.sync.aligned.m16n8k16.row.col.f32.bf16.bf16.f32 "
        "{%0,%1,%2,%3}, {%4,%5,%6,%7}, {%8,%9}, {%0,%1,%2,%3};"
        : "+f"(d[0]), "+f"(d[1]), "+f"(d[2]), "+f"(d[3])
        : "r"(a[0]), "r"(a[1]), "r"(a[2]), "r"(a[3]), "r"(b0), "r"(b1));
}

__device__ __forceinline__ float gelu_exact(float x) {
    return 0.5f * x * (1.0f + erff(x * 0.70710678118654752f));
}

__device__ __forceinline__ void split_bf16(float v, bf16& hi, bf16& lo) {
    hi = __float2bfloat16(v);
    lo = __float2bfloat16(v - __bfloat162float(hi));
}

// ---------------------------------------------------------------------------
// Weight prep: W[R,C] fp32 -> WT hi/lo [C,R] bf16. Block (32,8), grid (C/32,R/32)
// ---------------------------------------------------------------------------
__global__ void wprep_kernel(const float* __restrict__ W, bf16* __restrict__ Th,
                             bf16* __restrict__ Tl, int R, int C) {
    __shared__ float t[32][33];
    int c0 = blockIdx.x * 32, r0 = blockIdx.y * 32;
    #pragma unroll
    for (int j = 0; j < 4; j++)
        t[threadIdx.y + j * 8][threadIdx.x] =
            W[(size_t)(r0 + threadIdx.y + j * 8) * C + c0 + threadIdx.x];
    __syncthreads();
    #pragma unroll
    for (int j = 0; j < 4; j++) {
        float v = t[threadIdx.x][threadIdx.y + j * 8];
        bf16 hi, lo; split_bf16(v, hi, lo);
        size_t idx = (size_t)(c0 + threadIdx.y + j * 8) * R + r0 + threadIdx.x;
        Th[idx] = hi;
        Tl[idx] = lo;
    }
}

// ---------------------------------------------------------------------------
// LayerNorm -> bf16 hi/lo pair
// ---------------------------------------------------------------------------
__global__ void ln_pair_kernel(const float* __restrict__ x,
                               const float* __restrict__ g,
                               const float* __restrict__ beta,
                               bf16* __restrict__ yh, bf16* __restrict__ yl) {
    int row = blockIdx.x;
    int tid = threadIdx.x;
    const float4* xr = (const float4*)(x + (size_t)row * EMBD);
    float4 v = xr[tid];
    float s  = v.x + v.y + v.z + v.w;
    float ss = v.x*v.x + v.y*v.y + v.z*v.z + v.w*v.w;
    #pragma unroll
    for (int o = 16; o > 0; o >>= 1) {
        s  += __shfl_xor_sync(0xffffffffu, s,  o);
        ss += __shfl_xor_sync(0xffffffffu, ss, o);
    }
    __shared__ float sh[16];
    __shared__ float mean_s, rstd_s;
    int wid = tid >> 5, lane = tid & 31;
    if (lane == 0) { sh[wid] = s; sh[wid + 8] = ss; }
    __syncthreads();
    if (tid == 0) {
        float ts = 0.f, tss = 0.f;
        #pragma unroll
        for (int i = 0; i < 8; i++) { ts += sh[i]; tss += sh[i + 8]; }
        float mean = ts * (1.0f / EMBD);
        float var  = tss * (1.0f / EMBD) - mean * mean;
        mean_s = mean;
        rstd_s = rsqrtf(var + 1e-5f);
    }
    __syncthreads();
    float mean = mean_s, rstd = rstd_s;
    float4 gv = ((const float4*)g)[tid];
    float4 bv = ((const float4*)beta)[tid];
    float o[4];
    o[0] = (v.x - mean) * rstd * gv.x + bv.x;
    o[1] = (v.y - mean) * rstd * gv.y + bv.y;
    o[2] = (v.z - mean) * rstd * gv.z + bv.z;
    o[3] = (v.w - mean) * rstd * gv.w + bv.w;
    bf162* yh2 = (bf162*)(yh + (size_t)row * EMBD);
    bf162* yl2 = (bf162*)(yl + (size_t)row * EMBD);
    #pragma unroll
    for (int p = 0; p < 2; p++) {
        bf16 h0, l0, h1, l1;
        split_bf16(o[p * 2 + 0], h0, l0);
        split_bf16(o[p * 2 + 1], h1, l1);
        yh2[tid * 2 + p] = __halves2bfloat162(h0, h1);
        yl2[tid * 2 + p] = __halves2bfloat162(l0, l1);
    }
}

// ---------------------------------------------------------------------------
// bf16x3 mma.sync GEMM
// C[M,N] = Ahi/lo[M,K] @ (Bhi/lo[N,K])^T  (+ bias, + epilogue)
// 128x128 block, BK=32, 256 threads, 2-stage cp.async pipeline.
// ---------------------------------------------------------------------------
#define EPI_F32  0     // Cf = acc + bias
#define EPI_ADD  2     // Cf = acc + bias + add
#define EPI_GELU 1     // Chi/Clo = split(gelu(acc + bias))

#define TROW 80                       // bytes per smem row (32 bf16 + 16B pad)
#define TILE_B (128 * TROW)           // 10240
#define OFF_AH 0
#define OFF_AL (1 * TILE_B)
#define OFF_BH (2 * TILE_B)
#define OFF_BL (3 * TILE_B)
#define STAGE_B (4 * TILE_B)          // 40960
#define GEMM_SMEM (2 * STAGE_B)       // 81920

__device__ __forceinline__ void load_stage(
    uint32_t sdst, const bf16* __restrict__ Ah, const bf16* __restrict__ Al,
    const bf16* __restrict__ Bh, const bf16* __restrict__ Bl,
    int row0, int col0, int k0, int K, int tid) {
    int r  = tid >> 2;            // 0..63
    int cb = (tid & 3) * 16;      // byte chunk
    int ch = (tid & 3) * 8;       // halves
    size_t a0 = (size_t)(row0 + r)      * K + k0 + ch;
    size_t a1 = (size_t)(row0 + r + 64) * K + k0 + ch;
    size_t b0 = (size_t)(col0 + r)      * K + k0 + ch;
    size_t b1 = (size_t)(col0 + r + 64) * K + k0 + ch;
    uint32_t d0 = sdst + r * TROW + cb;
    uint32_t d1 = sdst + (r + 64) * TROW + cb;
    cp_async16(d0 + OFF_AH, Ah + a0);
    cp_async16(d1 + OFF_AH, Ah + a1);
    cp_async16(d0 + OFF_AL, Al + a0);
    cp_async16(d1 + OFF_AL, Al + a1);
    cp_async16(d0 + OFF_BH, Bh + b0);
    cp_async16(d1 + OFF_BH, Bh + b1);
    cp_async16(d0 + OFF_BL, Bl + b0);
    cp_async16(d1 + OFF_BL, Bl + b1);
}

template <int EPI>
__global__ void __launch_bounds__(256)
mma_gemm(const bf16* __restrict__ Ah, const bf16* __restrict__ Al,
         const bf16* __restrict__ Bh, const bf16* __restrict__ Bl,
         const float* __restrict__ bias, const float* __restrict__ add,
         float* __restrict__ Cf, bf16* __restrict__ Chi, bf16* __restrict__ Clo,
         int M, int N, int K) {
    extern __shared__ char smem[];
    const uint32_t sb = smem_to_u32(smem);
    const int tid  = threadIdx.x;
    const int lane = tid & 31;
    const int warp = tid >> 5;
    const int wm = warp >> 2;          // 0..1
    const int wn = warp & 3;           // 0..3
    const int row0 = blockIdx.y * 128;
    const int col0 = blockIdx.x * 128;

    float acc[4][4][4];
    #pragma unroll
    for (int m = 0; m < 4; m++)
        #pragma unroll
        for (int n = 0; n < 4; n++)
            #pragma unroll
            for (int e = 0; e < 4; e++) acc[m][n][e] = 0.f;

    const int KT = K / 32;

    load_stage(sb, Ah, Al, Bh, Bl, row0, col0, 0, K, tid);
    cp_commit();

    // per-warp ldmatrix base offsets (within a stage)
    const uint32_t a_off = (uint32_t)((wm * 64 + (lane & 15)) * TROW + (lane >> 4) * 16);
    const uint32_t b_off = (uint32_t)((wn * 32 + ((lane >> 4) << 3) + (lane & 7)) * TROW
                                      + ((lane >> 3) & 1) * 16);

    for (int kt = 0; kt < KT; kt++) {
        if (kt + 1 < KT) {
            load_stage(sb + ((kt + 1) & 1) * STAGE_B, Ah, Al, Bh, Bl,
                       row0, col0, (kt + 1) * 32, K, tid);
            cp_commit();
            cp_wait<1>();
        } else {
            cp_wait<0>();
        }
        __syncthreads();

        uint32_t s = sb + (kt & 1) * STAGE_B;
        #pragma unroll
        for (int ks = 0; ks < 2; ks++) {
            uint32_t ah[4][4], al[4][4], bh[2][4], bl[2][4];
            #pragma unroll
            for (int m = 0; m < 4; m++)
                ldmx4(ah[m], s + OFF_AH + a_off + ks * 32 + m * 16 * TROW);
            #pragma unroll
            for (int m = 0; m < 4; m++)
                ldmx4(al[m], s + OFF_AL + a_off + ks * 32 + m * 16 * TROW);
            #pragma unroll
            for (int n2 = 0; n2 < 2; n2++)
                ldmx4(bh[n2], s + OFF_BH + b_off + ks * 32 + n2 * 16 * TROW);
            #pragma unroll
            for (int n2 = 0; n2 < 2; n2++)
                ldmx4(bl[n2], s + OFF_BL + b_off + ks * 32 + n2 * 16 * TROW);

            #pragma unroll
            for (int m = 0; m < 4; m++)
                #pragma unroll
                for (int n = 0; n < 4; n++)
                    mma_bf16(acc[m][n], ah[m], bh[n >> 1][(n & 1) * 2],
                                               bh[n >> 1][(n & 1) * 2 + 1]);
            #pragma unroll
            for (int m = 0; m < 4; m++)
                #pragma unroll
                for (int n = 0; n < 4; n++)
                    mma_bf16(acc[m][n], ah[m], bl[n >> 1][(n & 1) * 2],
                                               bl[n >> 1][(n & 1) * 2 + 1]);
            #pragma unroll
            for (int m = 0; m < 4; m++)
                #pragma unroll
                for (int n = 0; n < 4; n++)
                    mma_bf16(acc[m][n], al[m], bh[n >> 1][(n & 1) * 2],
                                               bh[n >> 1][(n & 1) * 2 + 1]);
        }
        __syncthreads();
    }

    // Epilogue
    const int erow = row0 + wm * 64 + (lane >> 2);
    const int ecol = col0 + wn * 32 + (lane & 3) * 2;
    #pragma unroll
    for (int m = 0; m < 4; m++) {
        #pragma unroll
        for (int n = 0; n < 4; n++) {
            int c = ecol + n * 8;
            float b0 = bias[c], b1 = bias[c + 1];
            #pragma unroll
            for (int half = 0; half < 2; half++) {
                int r = erow + m * 16 + half * 8;
                float v0 = acc[m][n][half * 2 + 0] + b0;
                float v1 = acc[m][n][half * 2 + 1] + b1;
                if (EPI == EPI_ADD) {
                    const float2 av = *(const float2*)&add[(size_t)r * N + c];
                    v0 += av.x; v1 += av.y;
                }
                if (EPI == EPI_GELU) {
                    v0 = gelu_exact(v0);
                    v1 = gelu_exact(v1);
                    bf16 h0, l0, h1, l1;
                    split_bf16(v0, h0, l0);
                    split_bf16(v1, h1, l1);
                    *(bf162*)&Chi[(size_t)r * N + c] = __halves2bfloat162(h0, h1);
                    *(bf162*)&Clo[(size_t)r * N + c] = __halves2bfloat162(l0, l1);
                } else {
                    float2 o; o.x = v0; o.y = v1;
                    *(float2*)&Cf[(size_t)r * N + c] = o;
                }
            }
        }
    }
}

// ---------------------------------------------------------------------------
// Attention (fp32 flash-style), writes bf16 hi/lo pair output
// ---------------------------------------------------------------------------
__global__ void __launch_bounds__(128)
attn_kernel(const float* __restrict__ Q, const float* __restrict__ K,
            const float* __restrict__ V, bf16* __restrict__ Oh,
            bf16* __restrict__ Ol) {
    const int tid = threadIdx.x;
    const int q   = blockIdx.x * 128 + tid;
    const int h   = blockIdx.y;
    const int b   = blockIdx.z;
    const size_t base = (size_t)b * SEQ * EMBD + (size_t)h * HDIM;

    float qr[64];
    {
        const float4* qp = (const float4*)(Q + base + (size_t)q * EMBD);
        #pragma unroll
        for (int d4 = 0; d4 < 16; d4++) {
            float4 v = qp[d4];
            qr[d4 * 4 + 0] = v.x * 0.125f;
            qr[d4 * 4 + 1] = v.y * 0.125f;
            qr[d4 * 4 + 2] = v.z * 0.125f;
            qr[d4 * 4 + 3] = v.w * 0.125f;
        }
    }

    float m = -1e30f, l = 0.f;
    float acc[64];
    #pragma unroll
    for (int d = 0; d < 64; d++) acc[d] = 0.f;

    __shared__ float Ks[16][64];
    __shared__ float Vs[16][64];

    const int ntiles = (blockIdx.x + 1) * 8;
    const int lj = tid >> 3;
    const int lc = (tid & 7) * 8;

    for (int t = 0; t < ntiles; t++) {
        size_t krow = base + (size_t)(t * 16 + lj) * EMBD;
        *(float4*)&Ks[lj][lc]     = *(const float4*)(K + krow + lc);
        *(float4*)&Ks[lj][lc + 4] = *(const float4*)(K + krow + lc + 4);
        *(float4*)&Vs[lj][lc]     = *(const float4*)(V + krow + lc);
        *(float4*)&Vs[lj][lc + 4] = *(const float4*)(V + krow + lc + 4);
        __syncthreads();

        float sj[16];
        float tmax = -1e30f;
        #pragma unroll
        for (int jj = 0; jj < 16; jj++) {
            float s = 0.f;
            #pragma unroll
            for (int d4 = 0; d4 < 16; d4++) {
                float4 kv = *(const float4*)&Ks[jj][d4 * 4];
                s += qr[d4*4+0] * kv.x + qr[d4*4+1] * kv.y
                   + qr[d4*4+2] * kv.z + qr[d4*4+3] * kv.w;
            }
            int kidx = t * 16 + jj;
            bool ok = (kidx <= q) && (kidx % JOINED != (JOINED - 1));
            s = ok ? s : -1e30f;
            sj[jj] = s;
            tmax = fmaxf(tmax, s);
        }
        float mnew = fmaxf(m, tmax);
        float corr = __expf(m - mnew);
        l *= corr;
        #pragma unroll
        for (int d = 0; d < 64; d++) acc[d] *= corr;
        #pragma unroll
        for (int jj = 0; jj < 16; jj++) {
            float p = __expf(sj[jj] - mnew);
            l += p;
            #pragma unroll
            for (int d = 0; d < 64; d++) acc[d] += p * Vs[jj][d];
        }
        m = mnew;
        __syncthreads();
    }

    float inv = 1.0f / l;
    bf162* oh = (bf162*)(Oh + base + (size_t)q * EMBD);
    bf162* ol = (bf162*)(Ol + base + (size_t)q * EMBD);
    #pragma unroll
    for (int d2 = 0; d2 < 32; d2++) {
        float v0 = acc[d2 * 2 + 0] * inv;
        float v1 = acc[d2 * 2 + 1] * inv;
        bf16 h0, l0, h1, l1;
        split_bf16(v0, h0, l0);
        split_bf16(v1, h1, l1);
        oh[d2] = __halves2bfloat162(h0, h1);
        ol[d2] = __halves2bfloat162(l0, l1);
    }
}

// ---------------------------------------------------------------------------
// Host launcher
// ---------------------------------------------------------------------------
extern "C" void kernel_launch(void* const* d_in, const int* in_sizes, int n_in,
                              void* d_out, int out_size) {
    const float* hidden = (const float*)d_in[0];
    const float* Wq = (const float*)d_in[1];
    const float* bq = (const float*)d_in[2];
    const float* Wk = (const float*)d_in[3];
    const float* bk = (const float*)d_in[4];
    const float* Wv = (const float*)d_in[5];
    const float* bv = (const float*)d_in[6];
    const float* Wp = (const float*)d_in[7];
    const float* bp = (const float*)d_in[8];
    const float* ln1_g = (const float*)d_in[9];
    const float* ln1_b = (const float*)d_in[10];
    const float* ln2_g = (const float*)d_in[11];
    const float* ln2_b = (const float*)d_in[12];
    const float* W1 = (const float*)d_in[13];
    const float* b1 = (const float*)d_in[14];
    const float* W2 = (const float*)d_in[15];
    const float* b2 = (const float*)d_in[16];
    float* out = (float*)d_out;

    float *qb, *kb, *vb, *h1;
    bf16 *xlnh, *xlnl, *abh, *abl, *x2h, *x2l, *mhh, *mhl;
    bf16 *wqh, *wql, *wkh, *wkl, *wvh, *wvl, *wph, *wpl, *w1h, *w1l, *w2h, *w2l;
    cudaGetSymbolAddress((void**)&qb,  g_q);
    cudaGetSymbolAddress((void**)&kb,  g_k);
    cudaGetSymbolAddress((void**)&vb,  g_v);
    cudaGetSymbolAddress((void**)&h1,  g_h1);
    cudaGetSymbolAddress((void**)&xlnh, g_xlnh);
    cudaGetSymbolAddress((void**)&xlnl, g_xlnl);
    cudaGetSymbolAddress((void**)&abh,  g_abh);
    cudaGetSymbolAddress((void**)&abl,  g_abl);
    cudaGetSymbolAddress((void**)&x2h,  g_x2h);
    cudaGetSymbolAddress((void**)&x2l,  g_x2l);
    cudaGetSymbolAddress((void**)&mhh,  g_mhh);
    cudaGetSymbolAddress((void**)&mhl,  g_mhl);
    cudaGetSymbolAddress((void**)&wqh, g_wqh);  cudaGetSymbolAddress((void**)&wql, g_wql);
    cudaGetSymbolAddress((void**)&wkh, g_wkh);  cudaGetSymbolAddress((void**)&wkl, g_wkl);
    cudaGetSymbolAddress((void**)&wvh, g_wvh);  cudaGetSymbolAddress((void**)&wvl, g_wvl);
    cudaGetSymbolAddress((void**)&wph, g_wph);  cudaGetSymbolAddress((void**)&wpl, g_wpl);
    cudaGetSymbolAddress((void**)&w1h, g_w1h);  cudaGetSymbolAddress((void**)&w1l, g_w1l);
    cudaGetSymbolAddress((void**)&w2h, g_w2h);  cudaGetSymbolAddress((void**)&w2l, g_w2l);

    cudaFuncSetAttribute(mma_gemm<EPI_F32>,
                         cudaFuncAttributeMaxDynamicSharedMemorySize, GEMM_SMEM);
    cudaFuncSetAttribute(mma_gemm<EPI_ADD>,
                         cudaFuncAttributeMaxDynamicSharedMemorySize, GEMM_SMEM);
    cudaFuncSetAttribute(mma_gemm<EPI_GELU>,
                         cudaFuncAttributeMaxDynamicSharedMemorySize, GEMM_SMEM);

    // 0. Weight prep: transpose + hi/lo split
    dim3 tb(32, 8);
    wprep_kernel<<<dim3(EMBD/32, EMBD/32), tb>>>(Wq, wqh, wql, EMBD, EMBD);
    wprep_kernel<<<dim3(EMBD/32, EMBD/32), tb>>>(Wk, wkh, wkl, EMBD, EMBD);
    wprep_kernel<<<dim3(EMBD/32, EMBD/32), tb>>>(Wv, wvh, wvl, EMBD, EMBD);
    wprep_kernel<<<dim3(EMBD/32, EMBD/32), tb>>>(Wp, wph, wpl, EMBD, EMBD);
    wprep_kernel<<<dim3(FFN/32,  EMBD/32), tb>>>(W1, w1h, w1l, EMBD, FFN);
    wprep_kernel<<<dim3(EMBD/32, FFN/32),  tb>>>(W2, w2h, w2l, FFN, EMBD);

    // 1. LN1 -> hi/lo pair
    ln_pair_kernel<<<MROWS, 256>>>(hidden, ln1_g, ln1_b, xlnh, xlnl);

    // 2. QKV projections
    dim3 grid_d(EMBD / 128, MROWS / 128);
    mma_gemm<EPI_F32><<<grid_d, 256, GEMM_SMEM>>>(xlnh, xlnl, wqh, wql, bq, nullptr,
                                                  qb, nullptr, nullptr, MROWS, EMBD, EMBD);
    mma_gemm<EPI_F32><<<grid_d, 256, GEMM_SMEM>>>(xlnh, xlnl, wkh, wkl, bk, nullptr,
                                                  kb, nullptr, nullptr, MROWS, EMBD, EMBD);
    mma_gemm<EPI_F32><<<grid_d, 256, GEMM_SMEM>>>(xlnh, xlnl, wvh, wvl, bv, nullptr,
                                                  vb, nullptr, nullptr, MROWS, EMBD, EMBD);

    // 3. Attention -> hi/lo pair
    dim3 agrid(SEQ / 128, NHEAD, BATCH);
    attn_kernel<<<agrid, 128>>>(qb, kb, vb, abh, abl);

    // 4. Output projection + residual -> h1 (fp32)
    mma_gemm<EPI_ADD><<<grid_d, 256, GEMM_SMEM>>>(abh, abl, wph, wpl, bp, hidden,
                                                  h1, nullptr, nullptr, MROWS, EMBD, EMBD);

    // 5. LN2 -> hi/lo pair
    ln_pair_kernel<<<MROWS, 256>>>(h1, ln2_g, ln2_b, x2h, x2l);

    // 6. MLP up + GELU -> hi/lo pair
    dim3 grid_f(FFN / 128, MROWS / 128);
    mma_gemm<EPI_GELU><<<grid_f, 256, GEMM_SMEM>>>(x2h, x2l, w1h, w1l, b1, nullptr,
                                                   nullptr, mhh, mhl, MROWS, FFN, EMBD);

    // 7. MLP down + residual2 -> out
    mma_gemm<EPI_ADD><<<grid_d, 256, GEMM_SMEM>>>(mhh, mhl, w2h, w2l, b2, h1,
                                                  out, nullptr, nullptr, MROWS, EMBD, FFN);
}

// round 6
// speedup vs baseline: 3.0171x; 1.7908x over previous
#include <cuda_runtime.h>
#include <cuda_bf16.h>
#include <math.h>
#include <stdint.h>

// ---------------------------------------------------------------------------
// Problem constants
// ---------------------------------------------------------------------------
#define BATCH 2
#define SEQ   2048
#define EMBD  1024
#define NHEAD 16
#define HDIM  64
#define MROWS (BATCH * SEQ)          // 4096
#define FFN   (4 * EMBD)             // 4096
#define JOINED 25

typedef __nv_bfloat16 bf16;
typedef __nv_bfloat162 bf162;

// ---------------------------------------------------------------------------
// Scratch (device globals — no allocation allowed)
// ---------------------------------------------------------------------------
__device__ __align__(128) float g_h1 [MROWS * EMBD];
// bf16 hi/lo activation pairs
__device__ __align__(128) bf16 g_xlnh[MROWS * EMBD];
__device__ __align__(128) bf16 g_xlnl[MROWS * EMBD];
__device__ __align__(128) bf16 g_qh  [MROWS * EMBD];
__device__ __align__(128) bf16 g_ql  [MROWS * EMBD];
__device__ __align__(128) bf16 g_kh  [MROWS * EMBD];
__device__ __align__(128) bf16 g_kl  [MROWS * EMBD];
__device__ __align__(128) bf16 g_vh  [MROWS * EMBD];
__device__ __align__(128) bf16 g_vl  [MROWS * EMBD];
__device__ __align__(128) bf16 g_abh [MROWS * EMBD];
__device__ __align__(128) bf16 g_abl [MROWS * EMBD];
__device__ __align__(128) bf16 g_x2h [MROWS * EMBD];
__device__ __align__(128) bf16 g_x2l [MROWS * EMBD];
__device__ __align__(128) bf16 g_mhh [MROWS * FFN];
__device__ __align__(128) bf16 g_mhl [MROWS * FFN];
// bf16 hi/lo transposed weights [N, K]
__device__ __align__(128) bf16 g_wqh[EMBD * EMBD];
__device__ __align__(128) bf16 g_wql[EMBD * EMBD];
__device__ __align__(128) bf16 g_wkh[EMBD * EMBD];
__device__ __align__(128) bf16 g_wkl[EMBD * EMBD];
__device__ __align__(128) bf16 g_wvh[EMBD * EMBD];
__device__ __align__(128) bf16 g_wvl[EMBD * EMBD];
__device__ __align__(128) bf16 g_wph[EMBD * EMBD];
__device__ __align__(128) bf16 g_wpl[EMBD * EMBD];
__device__ __align__(128) bf16 g_w1h[FFN * EMBD];
__device__ __align__(128) bf16 g_w1l[FFN * EMBD];
__device__ __align__(128) bf16 g_w2h[EMBD * FFN];
__device__ __align__(128) bf16 g_w2l[EMBD * FFN];

// ---------------------------------------------------------------------------
// Small helpers
// ---------------------------------------------------------------------------
__device__ __forceinline__ uint32_t smem_to_u32(const void* p) {
    uint32_t a;
    asm("{ .reg .u64 t; cvta.to.shared.u64 t, %1; cvt.u32.u64 %0, t; }"
        : "=r"(a) : "l"(p));
    return a;
}

__device__ __forceinline__ void cp_async16(uint32_t dst, const void* src) {
    asm volatile("cp.async.cg.shared.global [%0], [%1], 16;" :: "r"(dst), "l"(src));
}
__device__ __forceinline__ void cp_commit() {
    asm volatile("cp.async.commit_group;");
}
template <int N>
__device__ __forceinline__ void cp_wait() {
    asm volatile("cp.async.wait_group %0;" :: "n"(N));
}

__device__ __forceinline__ void ldmx4(uint32_t (&r)[4], uint32_t addr) {
    asm volatile("ldmatrix.sync.aligned.m8n8.x4.shared.b16 {%0,%1,%2,%3}, [%4];"
        : "=r"(r[0]), "=r"(r[1]), "=r"(r[2]), "=r"(r[3]) : "r"(addr));
}

__device__ __forceinline__ void ldmx4t(uint32_t (&r)[4], uint32_t addr) {
    asm volatile("ldmatrix.sync.aligned.m8n8.x4.trans.shared.b16 {%0,%1,%2,%3}, [%4];"
        : "=r"(r[0]), "=r"(r[1]), "=r"(r[2]), "=r"(r[3]) : "r"(addr));
}

__device__ __forceinline__ void mma_bf16(float (&d)[4], const uint32_t (&a)[4],
                                         uint32_t b0, uint32_t b1) {
    asm volatile(
        "mma.sync.aligned.m16n8k16.row.col.f32.bf16.bf16.f32 "
        "{%0,%1,%2,%3}, {%4,%5,%6,%7}, {%8,%9}, {%0,%1,%2,%3};"
        : "+f"(d[0]), "+f"(d[1]), "+f"(d[2]), "+f"(d[3])
        : "r"(a[0]), "r"(a[1]), "r"(a[2]), "r"(a[3]), "r"(b0), "r"(b1));
}

__device__ __forceinline__ float gelu_exact(float x) {
    return 0.5f * x * (1.0f + erff(x * 0.70710678118654752f));
}

__device__ __forceinline__ void split_bf16(float v, bf16& hi, bf16& lo) {
    hi = __float2bfloat16(v);
    lo = __float2bfloat16(v - __bfloat162float(hi));
}

__device__ __forceinline__ uint32_t pack_bf162(bf16 a, bf16 b) {
    bf162 t = __halves2bfloat162(a, b);
    uint32_t r;
    memcpy(&r, &t, 4);
    return r;
}

// ---------------------------------------------------------------------------
// Weight prep: W[R,C] fp32 -> WT hi/lo [C,R] bf16.
// ---------------------------------------------------------------------------
__global__ void wprep_kernel(const float* __restrict__ W, bf16* __restrict__ Th,
                             bf16* __restrict__ Tl, int R, int C) {
    __shared__ float t[32][33];
    int c0 = blockIdx.x * 32, r0 = blockIdx.y * 32;
    #pragma unroll
    for (int j = 0; j < 4; j++)
        t[threadIdx.y + j * 8][threadIdx.x] =
            W[(size_t)(r0 + threadIdx.y + j * 8) * C + c0 + threadIdx.x];
    __syncthreads();
    #pragma unroll
    for (int j = 0; j < 4; j++) {
        float v = t[threadIdx.x][threadIdx.y + j * 8];
        bf16 hi, lo; split_bf16(v, hi, lo);
        size_t idx = (size_t)(c0 + threadIdx.y + j * 8) * R + r0 + threadIdx.x;
        Th[idx] = hi;
        Tl[idx] = lo;
    }
}

// ---------------------------------------------------------------------------
// LayerNorm -> bf16 hi/lo pair
// ---------------------------------------------------------------------------
__global__ void ln_pair_kernel(const float* __restrict__ x,
                               const float* __restrict__ g,
                               const float* __restrict__ beta,
                               bf16* __restrict__ yh, bf16* __restrict__ yl) {
    int row = blockIdx.x;
    int tid = threadIdx.x;
    const float4* xr = (const float4*)(x + (size_t)row * EMBD);
    float4 v = xr[tid];
    float s  = v.x + v.y + v.z + v.w;
    float ss = v.x*v.x + v.y*v.y + v.z*v.z + v.w*v.w;
    #pragma unroll
    for (int o = 16; o > 0; o >>= 1) {
        s  += __shfl_xor_sync(0xffffffffu, s,  o);
        ss += __shfl_xor_sync(0xffffffffu, ss, o);
    }
    __shared__ float sh[16];
    __shared__ float mean_s, rstd_s;
    int wid = tid >> 5, lane = tid & 31;
    if (lane == 0) { sh[wid] = s; sh[wid + 8] = ss; }
    __syncthreads();
    if (tid == 0) {
        float ts = 0.f, tss = 0.f;
        #pragma unroll
        for (int i = 0; i < 8; i++) { ts += sh[i]; tss += sh[i + 8]; }
        float mean = ts * (1.0f / EMBD);
        float var  = tss * (1.0f / EMBD) - mean * mean;
        mean_s = mean;
        rstd_s = rsqrtf(var + 1e-5f);
    }
    __syncthreads();
    float mean = mean_s, rstd = rstd_s;
    float4 gv = ((const float4*)g)[tid];
    float4 bv = ((const float4*)beta)[tid];
    float o[4];
    o[0] = (v.x - mean) * rstd * gv.x + bv.x;
    o[1] = (v.y - mean) * rstd * gv.y + bv.y;
    o[2] = (v.z - mean) * rstd * gv.z + bv.z;
    o[3] = (v.w - mean) * rstd * gv.w + bv.w;
    bf162* yh2 = (bf162*)(yh + (size_t)row * EMBD);
    bf162* yl2 = (bf162*)(yl + (size_t)row * EMBD);
    #pragma unroll
    for (int p = 0; p < 2; p++) {
        bf16 h0, l0, h1, l1;
        split_bf16(o[p * 2 + 0], h0, l0);
        split_bf16(o[p * 2 + 1], h1, l1);
        yh2[tid * 2 + p] = __halves2bfloat162(h0, h1);
        yl2[tid * 2 + p] = __halves2bfloat162(l0, l1);
    }
}

// ---------------------------------------------------------------------------
// bf16x3 mma.sync GEMM
// ---------------------------------------------------------------------------
#define EPI_F32  0     // Cf = acc + bias
#define EPI_GELU 1     // Chi/Clo = split(gelu(acc + bias))
#define EPI_ADD  2     // Cf = acc + bias + add
#define EPI_PAIR 3     // Chi/Clo = split(scale * (acc + bias))

#define TROW 80
#define TILE_B (128 * TROW)
#define OFF_AH 0
#define OFF_AL (1 * TILE_B)
#define OFF_BH (2 * TILE_B)
#define OFF_BL (3 * TILE_B)
#define STAGE_B (4 * TILE_B)
#define GEMM_SMEM (2 * STAGE_B)

__device__ __forceinline__ void load_stage(
    uint32_t sdst, const bf16* __restrict__ Ah, const bf16* __restrict__ Al,
    const bf16* __restrict__ Bh, const bf16* __restrict__ Bl,
    int row0, int col0, int k0, int K, int tid) {
    int r  = tid >> 2;
    int cb = (tid & 3) * 16;
    int ch = (tid & 3) * 8;
    size_t a0 = (size_t)(row0 + r)      * K + k0 + ch;
    size_t a1 = (size_t)(row0 + r + 64) * K + k0 + ch;
    size_t b0 = (size_t)(col0 + r)      * K + k0 + ch;
    size_t b1 = (size_t)(col0 + r + 64) * K + k0 + ch;
    uint32_t d0 = sdst + r * TROW + cb;
    uint32_t d1 = sdst + (r + 64) * TROW + cb;
    cp_async16(d0 + OFF_AH, Ah + a0);
    cp_async16(d1 + OFF_AH, Ah + a1);
    cp_async16(d0 + OFF_AL, Al + a0);
    cp_async16(d1 + OFF_AL, Al + a1);
    cp_async16(d0 + OFF_BH, Bh + b0);
    cp_async16(d1 + OFF_BH, Bh + b1);
    cp_async16(d0 + OFF_BL, Bl + b0);
    cp_async16(d1 + OFF_BL, Bl + b1);
}

template <int EPI>
__global__ void __launch_bounds__(256)
mma_gemm(const bf16* __restrict__ Ah, const bf16* __restrict__ Al,
         const bf16* __restrict__ Bh, const bf16* __restrict__ Bl,
         const float* __restrict__ bias, const float* __restrict__ add,
         float* __restrict__ Cf, bf16* __restrict__ Chi, bf16* __restrict__ Clo,
         int M, int N, int K, float scale) {
    extern __shared__ char smem[];
    const uint32_t sb = smem_to_u32(smem);
    const int tid  = threadIdx.x;
    const int lane = tid & 31;
    const int warp = tid >> 5;
    const int wm = warp >> 2;
    const int wn = warp & 3;
    const int row0 = blockIdx.y * 128;
    const int col0 = blockIdx.x * 128;

    float acc[4][4][4];
    #pragma unroll
    for (int m = 0; m < 4; m++)
        #pragma unroll
        for (int n = 0; n < 4; n++)
            #pragma unroll
            for (int e = 0; e < 4; e++) acc[m][n][e] = 0.f;

    const int KT = K / 32;

    load_stage(sb, Ah, Al, Bh, Bl, row0, col0, 0, K, tid);
    cp_commit();

    const uint32_t a_off = (uint32_t)((wm * 64 + (lane & 15)) * TROW + (lane >> 4) * 16);
    const uint32_t b_off = (uint32_t)((wn * 32 + ((lane >> 4) << 3) + (lane & 7)) * TROW
                                      + ((lane >> 3) & 1) * 16);

    for (int kt = 0; kt < KT; kt++) {
        if (kt + 1 < KT) {
            load_stage(sb + ((kt + 1) & 1) * STAGE_B, Ah, Al, Bh, Bl,
                       row0, col0, (kt + 1) * 32, K, tid);
            cp_commit();
            cp_wait<1>();
        } else {
            cp_wait<0>();
        }
        __syncthreads();

        uint32_t s = sb + (kt & 1) * STAGE_B;
        #pragma unroll
        for (int ks = 0; ks < 2; ks++) {
            uint32_t ah[4][4], al[4][4], bh[2][4], bl[2][4];
            #pragma unroll
            for (int m = 0; m < 4; m++)
                ldmx4(ah[m], s + OFF_AH + a_off + ks * 32 + m * 16 * TROW);
            #pragma unroll
            for (int m = 0; m < 4; m++)
                ldmx4(al[m], s + OFF_AL + a_off + ks * 32 + m * 16 * TROW);
            #pragma unroll
            for (int n2 = 0; n2 < 2; n2++)
                ldmx4(bh[n2], s + OFF_BH + b_off + ks * 32 + n2 * 16 * TROW);
            #pragma unroll
            for (int n2 = 0; n2 < 2; n2++)
                ldmx4(bl[n2], s + OFF_BL + b_off + ks * 32 + n2 * 16 * TROW);

            #pragma unroll
            for (int m = 0; m < 4; m++)
                #pragma unroll
                for (int n = 0; n < 4; n++)
                    mma_bf16(acc[m][n], ah[m], bh[n >> 1][(n & 1) * 2],
                                               bh[n >> 1][(n & 1) * 2 + 1]);
            #pragma unroll
            for (int m = 0; m < 4; m++)
                #pragma unroll
                for (int n = 0; n < 4; n++)
                    mma_bf16(acc[m][n], ah[m], bl[n >> 1][(n & 1) * 2],
                                               bl[n >> 1][(n & 1) * 2 + 1]);
            #pragma unroll
            for (int m = 0; m < 4; m++)
                #pragma unroll
                for (int n = 0; n < 4; n++)
                    mma_bf16(acc[m][n], al[m], bh[n >> 1][(n & 1) * 2],
                                               bh[n >> 1][(n & 1) * 2 + 1]);
        }
        __syncthreads();
    }

    // Epilogue
    const int erow = row0 + wm * 64 + (lane >> 2);
    const int ecol = col0 + wn * 32 + (lane & 3) * 2;
    #pragma unroll
    for (int m = 0; m < 4; m++) {
        #pragma unroll
        for (int n = 0; n < 4; n++) {
            int c = ecol + n * 8;
            float b0 = bias[c], b1 = bias[c + 1];
            #pragma unroll
            for (int half = 0; half < 2; half++) {
                int r = erow + m * 16 + half * 8;
                float v0 = acc[m][n][half * 2 + 0] + b0;
                float v1 = acc[m][n][half * 2 + 1] + b1;
                if (EPI == EPI_ADD) {
                    const float2 av = *(const float2*)&add[(size_t)r * N + c];
                    v0 += av.x; v1 += av.y;
                }
                if (EPI == EPI_GELU || EPI == EPI_PAIR) {
                    if (EPI == EPI_GELU) {
                        v0 = gelu_exact(v0);
                        v1 = gelu_exact(v1);
                    } else {
                        v0 *= scale;
                        v1 *= scale;
                    }
                    bf16 h0, l0, h1, l1;
                    split_bf16(v0, h0, l0);
                    split_bf16(v1, h1, l1);
                    *(bf162*)&Chi[(size_t)r * N + c] = __halves2bfloat162(h0, h1);
                    *(bf162*)&Clo[(size_t)r * N + c] = __halves2bfloat162(l0, l1);
                } else {
                    float2 o; o.x = v0; o.y = v1;
                    *(float2*)&Cf[(size_t)r * N + c] = o;
                }
            }
        }
    }
}

// ---------------------------------------------------------------------------
// Flash attention with mma.sync (bf16x3 everywhere)
// Grid (SEQ/64, NHEAD, BATCH), 128 threads (4 warps x 16 q-rows).
// ---------------------------------------------------------------------------
#define AT_TROW 144                   // 64 bf16 = 128B + 16B pad
#define AT_QH   0
#define AT_QL   9216
#define AT_KV0  18432                 // per stage: KH,KL,VH,VL each 9216
#define AT_STAGE 36864
#define AT_SMEM (18432 + 2 * 36864)   // 92160

__device__ __forceinline__ void attn_load_kv(
    uint32_t sb, size_t gbase, const bf16* __restrict__ Kh,
    const bf16* __restrict__ Kl, const bf16* __restrict__ Vh,
    const bf16* __restrict__ Vl, int kt, int stage, int tid) {
    int kb = kt * 64;
    #pragma unroll
    for (int i = 0; i < 4; i++) {
        int c = tid + i * 128;
        int r = c >> 3, sg = c & 7;
        size_t g = gbase + (size_t)(kb + r) * EMBD + sg * 8;
        uint32_t d = sb + AT_KV0 + stage * AT_STAGE + r * AT_TROW + sg * 16;
        cp_async16(d,             Kh + g);
        cp_async16(d + 9216,      Kl + g);
        cp_async16(d + 18432,     Vh + g);
        cp_async16(d + 27648,     Vl + g);
    }
}

__global__ void __launch_bounds__(128)
fattn_kernel(const bf16* __restrict__ Qh, const bf16* __restrict__ Ql,
             const bf16* __restrict__ Kh, const bf16* __restrict__ Kl,
             const bf16* __restrict__ Vh, const bf16* __restrict__ Vl,
             bf16* __restrict__ Oh, bf16* __restrict__ Ol) {
    extern __shared__ char smem[];
    const uint32_t sb = smem_to_u32(smem);
    const int tid = threadIdx.x;
    const int lane = tid & 31;
    const int wm = tid >> 5;           // warp 0..3 -> q rows wm*16..+15
    const int qt = blockIdx.x;
    const int h  = blockIdx.y;
    const int b  = blockIdx.z;
    const size_t gbase = (size_t)b * SEQ * EMBD + (size_t)h * HDIM;
    const int q0 = qt * 64;
    const int qrow0 = q0 + wm * 16 + (lane >> 2);
    const int qrow1 = qrow0 + 8;

    // load Q hi/lo (64 rows x 64 cols)
    #pragma unroll
    for (int i = 0; i < 4; i++) {
        int c = tid + i * 128;
        int r = c >> 3, sg = c & 7;
        size_t g = gbase + (size_t)(q0 + r) * EMBD + sg * 8;
        cp_async16(sb + AT_QH + r * AT_TROW + sg * 16, Qh + g);
        cp_async16(sb + AT_QL + r * AT_TROW + sg * 16, Ql + g);
    }
    attn_load_kv(sb, gbase, Kh, Kl, Vh, Vl, 0, 0, tid);
    cp_commit();

    float m0 = -1e30f, m1 = -1e30f, l0 = 0.f, l1 = 0.f;
    float acc[8][4];
    #pragma unroll
    for (int j = 0; j < 8; j++)
        #pragma unroll
        for (int e = 0; e < 4; e++) acc[j][e] = 0.f;

    uint32_t qhf[4][4], qlf[4][4];
    const int ntiles = qt + 1;
    const int ce = (lane & 3) * 2;

    for (int kt = 0; kt < ntiles; kt++) {
        if (kt + 1 < ntiles) {
            attn_load_kv(sb, gbase, Kh, Kl, Vh, Vl, kt + 1, (kt + 1) & 1, tid);
            cp_commit();
            cp_wait<1>();
        } else {
            cp_wait<0>();
        }
        __syncthreads();

        if (kt == 0) {
            uint32_t qa = sb + AT_QH + (wm * 16 + (lane & 15)) * AT_TROW + (lane >> 4) * 16;
            #pragma unroll
            for (int ks = 0; ks < 4; ks++) {
                ldmx4(qhf[ks], qa + ks * 32);
                ldmx4(qlf[ks], qa + 9216 + ks * 32);
            }
        }

        const uint32_t sK = sb + AT_KV0 + (kt & 1) * AT_STAGE;
        const uint32_t sV = sK + 18432;

        // ---- S = Q @ K^T (bf16x3) ----
        float c[8][4];
        #pragma unroll
        for (int j = 0; j < 8; j++)
            #pragma unroll
            for (int e = 0; e < 4; e++) c[j][e] = 0.f;

        const uint32_t bb = (((lane >> 4) << 3) + (lane & 7)) * AT_TROW
                            + ((lane >> 3) & 1) * 16;
        #pragma unroll
        for (int ks = 0; ks < 4; ks++) {
            uint32_t kbh[4][4], kbl[4][4];
            #pragma unroll
            for (int nn = 0; nn < 4; nn++) {
                ldmx4(kbh[nn], sK + nn * 16 * AT_TROW + bb + ks * 32);
                ldmx4(kbl[nn], sK + 9216 + nn * 16 * AT_TROW + bb + ks * 32);
            }
            #pragma unroll
            for (int j = 0; j < 8; j++) {
                uint32_t h0 = kbh[j >> 1][(j & 1) * 2], h1 = kbh[j >> 1][(j & 1) * 2 + 1];
                uint32_t lo0 = kbl[j >> 1][(j & 1) * 2], lo1 = kbl[j >> 1][(j & 1) * 2 + 1];
                mma_bf16(c[j], qhf[ks], h0, h1);
                mma_bf16(c[j], qhf[ks], lo0, lo1);
                mma_bf16(c[j], qlf[ks], h0, h1);
            }
        }

        // ---- mask + online softmax ----
        const int kb = kt * 64;
        float tmax0 = -1e30f, tmax1 = -1e30f;
        #pragma unroll
        for (int j = 0; j < 8; j++) {
            int ka = kb + j * 8 + ce;
            int kc = ka + 1;
            bool okA = ((ka + 1) % JOINED != 0);
            bool okB = ((kc + 1) % JOINED != 0);
            float s0 = (okA && ka <= qrow0) ? c[j][0] : -1e30f;
            float s1 = (okB && kc <= qrow0) ? c[j][1] : -1e30f;
            float s2 = (okA && ka <= qrow1) ? c[j][2] : -1e30f;
            float s3 = (okB && kc <= qrow1) ? c[j][3] : -1e30f;
            c[j][0] = s0; c[j][1] = s1; c[j][2] = s2; c[j][3] = s3;
            tmax0 = fmaxf(tmax0, fmaxf(s0, s1));
            tmax1 = fmaxf(tmax1, fmaxf(s2, s3));
        }
        tmax0 = fmaxf(tmax0, __shfl_xor_sync(0xffffffffu, tmax0, 1));
        tmax0 = fmaxf(tmax0, __shfl_xor_sync(0xffffffffu, tmax0, 2));
        tmax1 = fmaxf(tmax1, __shfl_xor_sync(0xffffffffu, tmax1, 1));
        tmax1 = fmaxf(tmax1, __shfl_xor_sync(0xffffffffu, tmax1, 2));
        float mn0 = fmaxf(m0, tmax0), mn1 = fmaxf(m1, tmax1);
        float cr0 = __expf(m0 - mn0), cr1 = __expf(m1 - mn1);
        m0 = mn0; m1 = mn1;

        uint32_t pah[4][4], pal[4][4];
        float ps0 = 0.f, ps1 = 0.f;
        #pragma unroll
        for (int j = 0; j < 8; j++) {
            float p0 = __expf(c[j][0] - mn0);
            float p1 = __expf(c[j][1] - mn0);
            float p2 = __expf(c[j][2] - mn1);
            float p3 = __expf(c[j][3] - mn1);
            ps0 += p0 + p1;
            ps1 += p2 + p3;
            bf16 h0, lo0, h1, lo1, h2, lo2, h3, lo3;
            split_bf16(p0, h0, lo0); split_bf16(p1, h1, lo1);
            split_bf16(p2, h2, lo2); split_bf16(p3, h3, lo3);
            int t = j >> 1, rr = (j & 1) * 2;
            pah[t][rr]     = pack_bf162(h0, h1);
            pah[t][rr + 1] = pack_bf162(h2, h3);
            pal[t][rr]     = pack_bf162(lo0, lo1);
            pal[t][rr + 1] = pack_bf162(lo2, lo3);
        }
        l0 = l0 * cr0 + ps0;
        l1 = l1 * cr1 + ps1;
        #pragma unroll
        for (int j = 0; j < 8; j++) {
            acc[j][0] *= cr0; acc[j][1] *= cr0;
            acc[j][2] *= cr1; acc[j][3] *= cr1;
        }

        // ---- O += P @ V (bf16x3) ----
        const uint32_t vrow = (lane & 7) + ((lane >> 3) & 1) * 8;
        const uint32_t vcb  = (lane >> 4) * 16;
        #pragma unroll
        for (int t = 0; t < 4; t++) {
            uint32_t vbh[4][4], vbl[4][4];
            uint32_t vb = sV + (t * 16 + vrow) * AT_TROW + vcb;
            #pragma unroll
            for (int jj = 0; jj < 4; jj++) {
                ldmx4t(vbh[jj], vb + jj * 32);
                ldmx4t(vbl[jj], vb + 9216 + jj * 32);
            }
            #pragma unroll
            for (int jj = 0; jj < 4; jj++) {
                mma_bf16(acc[2 * jj],     pah[t], vbh[jj][0], vbh[jj][1]);
                mma_bf16(acc[2 * jj + 1], pah[t], vbh[jj][2], vbh[jj][3]);
                mma_bf16(acc[2 * jj],     pal[t], vbh[jj][0], vbh[jj][1]);
                mma_bf16(acc[2 * jj + 1], pal[t], vbh[jj][2], vbh[jj][3]);
                mma_bf16(acc[2 * jj],     pah[t], vbl[jj][0], vbl[jj][1]);
                mma_bf16(acc[2 * jj + 1], pah[t], vbl[jj][2], vbl[jj][3]);
            }
        }
        __syncthreads();
    }

    // final normalize + write hi/lo
    l0 += __shfl_xor_sync(0xffffffffu, l0, 1);
    l0 += __shfl_xor_sync(0xffffffffu, l0, 2);
    l1 += __shfl_xor_sync(0xffffffffu, l1, 1);
    l1 += __shfl_xor_sync(0xffffffffu, l1, 2);
    float inv0 = 1.0f / l0, inv1 = 1.0f / l1;
    size_t o0 = (size_t)(b * SEQ + qrow0) * EMBD + h * HDIM;
    size_t o1 = (size_t)(b * SEQ + qrow1) * EMBD + h * HDIM;
    #pragma unroll
    for (int j = 0; j < 8; j++) {
        int cc = j * 8 + ce;
        float v0 = acc[j][0] * inv0, v1 = acc[j][1] * inv0;
        float v2 = acc[j][2] * inv1, v3 = acc[j][3] * inv1;
        bf16 h0, lo0, h1, lo1, h2, lo2, h3, lo3;
        split_bf16(v0, h0, lo0); split_bf16(v1, h1, lo1);
        split_bf16(v2, h2, lo2); split_bf16(v3, h3, lo3);
        *(bf162*)&Oh[o0 + cc] = __halves2bfloat162(h0, h1);
        *(bf162*)&Ol[o0 + cc] = __halves2bfloat162(lo0, lo1);
        *(bf162*)&Oh[o1 + cc] = __halves2bfloat162(h2, h3);
        *(bf162*)&Ol[o1 + cc] = __halves2bfloat162(lo2, lo3);
    }
}

// ---------------------------------------------------------------------------
// Host launcher
// ---------------------------------------------------------------------------
extern "C" void kernel_launch(void* const* d_in, const int* in_sizes, int n_in,
                              void* d_out, int out_size) {
    const float* hidden = (const float*)d_in[0];
    const float* Wq = (const float*)d_in[1];
    const float* bq = (const float*)d_in[2];
    const float* Wk = (const float*)d_in[3];
    const float* bk = (const float*)d_in[4];
    const float* Wv = (const float*)d_in[5];
    const float* bv = (const float*)d_in[6];
    const float* Wp = (const float*)d_in[7];
    const float* bp = (const float*)d_in[8];
    const float* ln1_g = (const float*)d_in[9];
    const float* ln1_b = (const float*)d_in[10];
    const float* ln2_g = (const float*)d_in[11];
    const float* ln2_b = (const float*)d_in[12];
    const float* W1 = (const float*)d_in[13];
    const float* b1 = (const float*)d_in[14];
    const float* W2 = (const float*)d_in[15];
    const float* b2 = (const float*)d_in[16];
    float* out = (float*)d_out;

    float *h1;
    bf16 *xlnh, *xlnl, *qh, *ql, *kh, *kl, *vh, *vl, *abh, *abl, *x2h, *x2l, *mhh, *mhl;
    bf16 *wqh, *wql, *wkh, *wkl, *wvh, *wvl, *wph, *wpl, *w1h, *w1l, *w2h, *w2l;
    cudaGetSymbolAddress((void**)&h1,  g_h1);
    cudaGetSymbolAddress((void**)&xlnh, g_xlnh);
    cudaGetSymbolAddress((void**)&xlnl, g_xlnl);
    cudaGetSymbolAddress((void**)&qh, g_qh);  cudaGetSymbolAddress((void**)&ql, g_ql);
    cudaGetSymbolAddress((void**)&kh, g_kh);  cudaGetSymbolAddress((void**)&kl, g_kl);
    cudaGetSymbolAddress((void**)&vh, g_vh);  cudaGetSymbolAddress((void**)&vl, g_vl);
    cudaGetSymbolAddress((void**)&abh, g_abh);
    cudaGetSymbolAddress((void**)&abl, g_abl);
    cudaGetSymbolAddress((void**)&x2h, g_x2h);
    cudaGetSymbolAddress((void**)&x2l, g_x2l);
    cudaGetSymbolAddress((void**)&mhh, g_mhh);
    cudaGetSymbolAddress((void**)&mhl, g_mhl);
    cudaGetSymbolAddress((void**)&wqh, g_wqh);  cudaGetSymbolAddress((void**)&wql, g_wql);
    cudaGetSymbolAddress((void**)&wkh, g_wkh);  cudaGetSymbolAddress((void**)&wkl, g_wkl);
    cudaGetSymbolAddress((void**)&wvh, g_wvh);  cudaGetSymbolAddress((void**)&wvl, g_wvl);
    cudaGetSymbolAddress((void**)&wph, g_wph);  cudaGetSymbolAddress((void**)&wpl, g_wpl);
    cudaGetSymbolAddress((void**)&w1h, g_w1h);  cudaGetSymbolAddress((void**)&w1l, g_w1l);
    cudaGetSymbolAddress((void**)&w2h, g_w2h);  cudaGetSymbolAddress((void**)&w2l, g_w2l);

    cudaFuncSetAttribute(mma_gemm<EPI_F32>,
                         cudaFuncAttributeMaxDynamicSharedMemorySize, GEMM_SMEM);
    cudaFuncSetAttribute(mma_gemm<EPI_ADD>,
                         cudaFuncAttributeMaxDynamicSharedMemorySize, GEMM_SMEM);
    cudaFuncSetAttribute(mma_gemm<EPI_GELU>,
                         cudaFuncAttributeMaxDynamicSharedMemorySize, GEMM_SMEM);
    cudaFuncSetAttribute(mma_gemm<EPI_PAIR>,
                         cudaFuncAttributeMaxDynamicSharedMemorySize, GEMM_SMEM);
    cudaFuncSetAttribute(fattn_kernel,
                         cudaFuncAttributeMaxDynamicSharedMemorySize, AT_SMEM);

    // 0. Weight prep
    dim3 tb(32, 8);
    wprep_kernel<<<dim3(EMBD/32, EMBD/32), tb>>>(Wq, wqh, wql, EMBD, EMBD);
    wprep_kernel<<<dim3(EMBD/32, EMBD/32), tb>>>(Wk, wkh, wkl, EMBD, EMBD);
    wprep_kernel<<<dim3(EMBD/32, EMBD/32), tb>>>(Wv, wvh, wvl, EMBD, EMBD);
    wprep_kernel<<<dim3(EMBD/32, EMBD/32), tb>>>(Wp, wph, wpl, EMBD, EMBD);
    wprep_kernel<<<dim3(FFN/32,  EMBD/32), tb>>>(W1, w1h, w1l, EMBD, FFN);
    wprep_kernel<<<dim3(EMBD/32, FFN/32),  tb>>>(W2, w2h, w2l, FFN, EMBD);

    // 1. LN1
    ln_pair_kernel<<<MROWS, 256>>>(hidden, ln1_g, ln1_b, xlnh, xlnl);

    // 2. QKV projections -> bf16 hi/lo pairs (Q pre-scaled by 1/8)
    dim3 grid_d(EMBD / 128, MROWS / 128);
    mma_gemm<EPI_PAIR><<<grid_d, 256, GEMM_SMEM>>>(xlnh, xlnl, wqh, wql, bq, nullptr,
                                                   nullptr, qh, ql, MROWS, EMBD, EMBD, 0.125f);
    mma_gemm<EPI_PAIR><<<grid_d, 256, GEMM_SMEM>>>(xlnh, xlnl, wkh, wkl, bk, nullptr,
                                                   nullptr, kh, kl, MROWS, EMBD, EMBD, 1.0f);
    mma_gemm<EPI_PAIR><<<grid_d, 256, GEMM_SMEM>>>(xlnh, xlnl, wvh, wvl, bv, nullptr,
                                                   nullptr, vh, vl, MROWS, EMBD, EMBD, 1.0f);

    // 3. Flash attention (tensor cores)
    dim3 agrid(SEQ / 64, NHEAD, BATCH);
    fattn_kernel<<<agrid, 128, AT_SMEM>>>(qh, ql, kh, kl, vh, vl, abh, abl);

    // 4. Output projection + residual -> h1 (fp32)
    mma_gemm<EPI_ADD><<<grid_d, 256, GEMM_SMEM>>>(abh, abl, wph, wpl, bp, hidden,
                                                  h1, nullptr, nullptr, MROWS, EMBD, EMBD, 1.0f);

    // 5. LN2
    ln_pair_kernel<<<MROWS, 256>>>(h1, ln2_g, ln2_b, x2h, x2l);

    // 6. MLP up + GELU
    dim3 grid_f(FFN / 128, MROWS / 128);
    mma_gemm<EPI_GELU><<<grid_f, 256, GEMM_SMEM>>>(x2h, x2l, w1h, w1l, b1, nullptr,
                                                   nullptr, mhh, mhl, MROWS, FFN, EMBD, 1.0f);

    // 7. MLP down + residual2 -> out
    mma_gemm<EPI_ADD><<<grid_d, 256, GEMM_SMEM>>>(mhh, mhl, w2h, w2l, b2, h1,
                                                  out, nullptr, nullptr, MROWS, EMBD, FFN, 1.0f);
}